// round 1
// baseline (speedup 1.0000x reference)
#include <cuda_runtime.h>
#include <math.h>

// Problem constants (fixed by setup_inputs): B=8, D=8, H=56, W=56, C=128,
// 4 heads x 32. Window sizes (8,7,7). All pads are zero.
static constexpr int CDIM   = 128;
static constexpr int NT_MAX = 56;                 // max tokens per window
static constexpr int RB_FLOATS  = 16384;          // weight-chunk / score scratch (64KB)
static constexpr int SMEM_FLOATS = 4 * NT_MAX * CDIM + RB_FLOATS; // q,k,v,xa + rb = 45056
static constexpr int SMEM_BYTES  = SMEM_FLOATS * 4 + 64 * 4;      // + tokidx

// (window, token) -> flat global token index. Any consistent enumeration of
// windows/tokens is valid: attention is per-window and we map back by token.
template <int BRANCH>
__device__ __forceinline__ int tok_index(int win, int tt) {
    if (BRANCH == 0) {                 // xy: windows (b, d, hb, wb), token (hh, ww)
        int b  = win >> 9;
        int d  = (win >> 6) & 7;
        int hb = (win >> 3) & 7;
        int wb = win & 7;
        int hh = tt / 7, wq = tt - hh * 7;
        return ((b * 8 + d) * 56 + hb * 7 + hh) * 56 + wb * 7 + wq;
    } else if (BRANCH == 1) {          // th: windows (b, hb, w), token (dd, hh)
        int b  = win / 448;
        int r  = win - b * 448;
        int hb = r / 56;
        int w  = r - hb * 56;
        int dd = tt / 7, hh = tt - dd * 7;
        return ((b * 8 + dd) * 56 + hb * 7 + hh) * 56 + w;
    } else {                           // tw: windows (b, h, wb), token (dd, ww)
        int b  = win / 448;
        int r  = win - b * 448;
        int h  = r >> 3;
        int wb = r & 7;
        int dd = tt / 7, wq = tt - dd * 7;
        return ((b * 8 + dd) * 56 + h) * 56 + wb * 7 + wq;
    }
}

// One CTA per window. Fully fused: x load -> qkv GEMM -> 4-head attention
// -> proj GEMM -> global store/accumulate. 256 threads (8 warps).
// Thread GEMM tile: 7 rows x 4 cols (float4). Smem regions:
//   qs/ks/vs : 56x128 each
//   xa       : 56x128  (x, later attention output)
//   rb       : 16384 floats (weight chunk 128x128, later scores 4*n*n)
template <int BRANCH, int NTOK>
__global__ void __launch_bounds__(256, 1)
win_attn_kernel(const float* __restrict__ x,
                const float* __restrict__ qkvw, const float* __restrict__ qkvb,
                const float* __restrict__ projw, const float* __restrict__ projb,
                float* __restrict__ out)
{
    extern __shared__ float sm[];
    float* qs = sm;
    float* ks = qs + NT_MAX * CDIM;
    float* vs = ks + NT_MAX * CDIM;
    float* xa = vs + NT_MAX * CDIM;
    float* rb = xa + NT_MAX * CDIM;
    int*   tokidx = (int*)(sm + SMEM_FLOATS);

    const int t    = threadIdx.x;
    const int lane = t & 31;
    const int wrp  = t >> 5;
    const int win  = blockIdx.x;
    const int colc = lane * 4;
    constexpr int RPT = 7;  // ceil(56/8) rows per thread

    if (t < NTOK) tokidx[t] = tok_index<BRANCH>(win, t);

    // Load window tokens into xa (coalesced float4)
    for (int idx = t; idx < NTOK * 32; idx += 256) {
        int r  = idx >> 5;
        int c4 = idx & 31;
        ((float4*)xa)[r * 32 + c4] =
            ((const float4*)x)[(size_t)tok_index<BRANCH>(win, r) * 32 + c4];
    }
    __syncthreads();

    // ---- QKV GEMM: n x 128 @ 128 x 384, in 3 chunks of 128 cols (q, k, v) ----
    const float qscale = 0.1767766952966369f;  // 32^-0.5
    #pragma unroll
    for (int cc = 0; cc < 3; cc++) {
        for (int idx = t; idx < 128 * 32; idx += 256) {
            int kk = idx >> 5;
            int c4 = idx & 31;
            ((float4*)rb)[idx] = ((const float4*)qkvw)[(kk * 384 + cc * 128) / 4 + c4];
        }
        __syncthreads();

        float4 bias = *(const float4*)&qkvb[cc * 128 + colc];
        float4 acc[RPT];
        #pragma unroll
        for (int rr = 0; rr < RPT; rr++) acc[rr] = bias;

        #pragma unroll 8
        for (int kk = 0; kk < 128; kk++) {
            float4 wv = ((const float4*)rb)[kk * 32 + lane];
            #pragma unroll
            for (int rr = 0; rr < RPT; rr++) {
                float xv = xa[(wrp + rr * 8) * CDIM + kk];  // broadcast within warp
                acc[rr].x = fmaf(xv, wv.x, acc[rr].x);
                acc[rr].y = fmaf(xv, wv.y, acc[rr].y);
                acc[rr].z = fmaf(xv, wv.z, acc[rr].z);
                acc[rr].w = fmaf(xv, wv.w, acc[rr].w);
            }
        }

        float* dst = (cc == 0) ? qs : (cc == 1 ? ks : vs);
        float  mul = (cc == 0) ? qscale : 1.0f;
        #pragma unroll
        for (int rr = 0; rr < RPT; rr++) {
            int r = wrp + rr * 8;
            if (r < NTOK) {
                float4 a = acc[rr];
                a.x *= mul; a.y *= mul; a.z *= mul; a.w *= mul;
                *(float4*)&dst[r * CDIM + colc] = a;
            }
        }
        __syncthreads();
    }

    // ---- Scores: s[h][i][j] = q[i,h*32:] . k[j,h*32:] (scale folded into q) ----
    float* sc = rb;
    constexpr int NN = NTOK * NTOK;
    for (int idx = t; idx < 4 * NN; idx += 256) {
        int h   = idx / NN;
        int rem = idx - h * NN;
        int i   = rem / NTOK;
        int j   = rem - i * NTOK;
        const float4* qp = (const float4*)&qs[i * CDIM + h * 32];
        const float4* kp = (const float4*)&ks[j * CDIM + h * 32];
        float a = 0.f;
        #pragma unroll
        for (int kk = 0; kk < 8; kk++) {
            float4 qv = qp[kk], kv = kp[kk];
            a = fmaf(qv.x, kv.x, a); a = fmaf(qv.y, kv.y, a);
            a = fmaf(qv.z, kv.z, a); a = fmaf(qv.w, kv.w, a);
        }
        sc[idx] = a;
    }
    __syncthreads();

    // ---- Softmax over j, one warp per row (4*NTOK rows) ----
    for (int row = wrp; row < 4 * NTOK; row += 8) {
        float* sr = sc + row * NTOK;
        float m = -1e30f;
        for (int j = lane; j < NTOK; j += 32) m = fmaxf(m, sr[j]);
        #pragma unroll
        for (int off = 16; off; off >>= 1)
            m = fmaxf(m, __shfl_xor_sync(0xffffffffu, m, off));
        float ssum = 0.f;
        for (int j = lane; j < NTOK; j += 32) {
            float e = __expf(sr[j] - m);
            sr[j] = e;
            ssum += e;
        }
        #pragma unroll
        for (int off = 16; off; off >>= 1)
            ssum += __shfl_xor_sync(0xffffffffu, ssum, off);
        float inv = 1.0f / ssum;
        for (int j = lane; j < NTOK; j += 32) sr[j] *= inv;
    }
    __syncthreads();

    // ---- attn @ v -> xa (per-head: h determined by the column group) ----
    {
        const int h = lane >> 3;   // colc / 32
        float4 acc[RPT];
        #pragma unroll
        for (int rr = 0; rr < RPT; rr++) acc[rr] = make_float4(0.f, 0.f, 0.f, 0.f);
        for (int j = 0; j < NTOK; j++) {
            float4 vv = *(const float4*)&vs[j * CDIM + colc];
            #pragma unroll
            for (int rr = 0; rr < RPT; rr++) {
                int i = wrp + rr * 8;
                float sv = sc[(h * NTOK + i) * NTOK + j];
                acc[rr].x = fmaf(sv, vv.x, acc[rr].x);
                acc[rr].y = fmaf(sv, vv.y, acc[rr].y);
                acc[rr].z = fmaf(sv, vv.z, acc[rr].z);
                acc[rr].w = fmaf(sv, vv.w, acc[rr].w);
            }
        }
        #pragma unroll
        for (int rr = 0; rr < RPT; rr++) {
            int i = wrp + rr * 8;
            if (i < NTOK) *(float4*)&xa[i * CDIM + colc] = acc[rr];
        }
    }
    __syncthreads();

    // ---- Proj GEMM: n x 128 @ 128 x 128, then store/accumulate to global ----
    for (int idx = t; idx < 128 * 32; idx += 256)
        ((float4*)rb)[idx] = ((const float4*)projw)[idx];
    __syncthreads();
    {
        float4 bias = *(const float4*)&projb[colc];
        float4 acc[RPT];
        #pragma unroll
        for (int rr = 0; rr < RPT; rr++) acc[rr] = bias;

        #pragma unroll 8
        for (int kk = 0; kk < 128; kk++) {
            float4 wv = ((const float4*)rb)[kk * 32 + lane];
            #pragma unroll
            for (int rr = 0; rr < RPT; rr++) {
                float xv = xa[(wrp + rr * 8) * CDIM + kk];
                acc[rr].x = fmaf(xv, wv.x, acc[rr].x);
                acc[rr].y = fmaf(xv, wv.y, acc[rr].y);
                acc[rr].z = fmaf(xv, wv.z, acc[rr].z);
                acc[rr].w = fmaf(xv, wv.w, acc[rr].w);
            }
        }

        #pragma unroll
        for (int rr = 0; rr < RPT; rr++) {
            int r = wrp + rr * 8;
            if (r < NTOK) {
                size_t o = (size_t)tokidx[r] * CDIM + colc;
                float4 a = acc[rr];
                if (BRANCH != 0) {
                    float4 cur = *(const float4*)&out[o];
                    a.x += cur.x; a.y += cur.y; a.z += cur.z; a.w += cur.w;
                }
                *(float4*)&out[o] = a;
            }
        }
    }
}

extern "C" void kernel_launch(void* const* d_in, const int* in_sizes, int n_in,
                              void* d_out, int out_size)
{
    const float* x         = (const float*)d_in[0];
    const float* qkv_w     = (const float*)d_in[1];
    const float* qkv_b     = (const float*)d_in[2];
    const float* qkv_th_w  = (const float*)d_in[3];
    const float* qkv_th_b  = (const float*)d_in[4];
    const float* qkv_tw_w  = (const float*)d_in[5];
    const float* qkv_tw_b  = (const float*)d_in[6];
    const float* proj_w    = (const float*)d_in[7];
    const float* proj_b    = (const float*)d_in[8];
    const float* proj_th_w = (const float*)d_in[9];
    const float* proj_th_b = (const float*)d_in[10];
    const float* proj_tw_w = (const float*)d_in[11];
    const float* proj_tw_b = (const float*)d_in[12];
    float* out = (float*)d_out;

    // >48KB dynamic smem needs an explicit opt-in (idempotent; not a stream op).
    cudaFuncSetAttribute(win_attn_kernel<0, 49>,
                         cudaFuncAttributeMaxDynamicSharedMemorySize, SMEM_BYTES);
    cudaFuncSetAttribute(win_attn_kernel<1, 56>,
                         cudaFuncAttributeMaxDynamicSharedMemorySize, SMEM_BYTES);
    cudaFuncSetAttribute(win_attn_kernel<2, 56>,
                         cudaFuncAttributeMaxDynamicSharedMemorySize, SMEM_BYTES);

    // Branch xy writes (covers every output element exactly once),
    // th / tw accumulate. Same stream -> ordered, no atomics needed.
    win_attn_kernel<0, 49><<<4096, 256, SMEM_BYTES>>>(
        x, qkv_w, qkv_b, proj_w, proj_b, out);
    win_attn_kernel<1, 56><<<3584, 256, SMEM_BYTES>>>(
        x, qkv_th_w, qkv_th_b, proj_th_w, proj_th_b, out);
    win_attn_kernel<2, 56><<<3584, 256, SMEM_BYTES>>>(
        x, qkv_tw_w, qkv_tw_b, proj_tw_w, proj_tw_b, out);
}

// round 2
// speedup vs baseline: 4.1039x; 4.1039x over previous
#include <cuda_runtime.h>
#include <cstdint>

// Problem constants: B=8, D=8, H=W=56, C=128, 4 heads x 32, windows (8,7,7),
// all pads zero. Branch xy: 4096 windows x 49 tok; th/tw: 3584 x 56.
static constexpr int S    = 132;   // stride (floats) for x/q/k/v rows (conflict-free A frags)
static constexpr int WS   = 136;   // stride for weight rows (conflict-free B frags)
static constexpr int SCS  = 60;    // stride for score rows (conflict-free P frags + stores)
static constexpr int ROWS = 64;    // padded token rows (4 m-tiles of 16)

static constexpr int OFF_Q  = 0;
static constexpr int OFF_K  = ROWS * S;
static constexpr int OFF_V  = 2 * ROWS * S;
static constexpr int OFF_X  = 3 * ROWS * S;           // x, later attention output
static constexpr int OFF_RB = 4 * ROWS * S;           // weights 128xWS  OR  scores 4x64xSCS
static constexpr int RB_FLOATS   = 128 * WS;          // 17408 >= 4*64*60 = 15360
static constexpr int SMEM_FLOATS = OFF_RB + RB_FLOATS;        // 51200
static constexpr int SMEM_BYTES  = SMEM_FLOATS * 4 + 64 * 4;  // + tokidx = 205056 B

// (window, token) -> flat global token index.
template <int BRANCH>
__device__ __forceinline__ int tok_index(int win, int tt) {
    if (BRANCH == 0) {                 // xy: windows (b, d, hb, wb), token (hh, ww)
        int b  = win >> 9;
        int d  = (win >> 6) & 7;
        int hb = (win >> 3) & 7;
        int wb = win & 7;
        int hh = tt / 7, wq = tt - hh * 7;
        return ((b * 8 + d) * 56 + hb * 7 + hh) * 56 + wb * 7 + wq;
    } else if (BRANCH == 1) {          // th: windows (b, hb, w), token (dd, hh)
        int b  = win / 448;
        int r  = win - b * 448;
        int hb = r / 56;
        int w  = r - hb * 56;
        int dd = tt / 7, hh = tt - dd * 7;
        return ((b * 8 + dd) * 56 + hb * 7 + hh) * 56 + w;
    } else {                           // tw: windows (b, h, wb), token (dd, ww)
        int b  = win / 448;
        int r  = win - b * 448;
        int h  = r >> 3;
        int wb = r & 7;
        int dd = tt / 7, wq = tt - dd * 7;
        return ((b * 8 + dd) * 56 + h) * 56 + wb * 7 + wq;
    }
}

// Round-to-nearest fp32 -> tf32 (keeps zero-mean error; raw truncation would
// add a systematic -1e-3 relative bias across K=128 sums).
__device__ __forceinline__ uint32_t f2tf(float f) {
    uint32_t r; asm("cvt.rna.tf32.f32 %0, %1;" : "=r"(r) : "f"(f)); return r;
}

// D += A(16x8) * B(8x8), tf32 in, fp32 accumulate.
__device__ __forceinline__ void mma8(float4& d, const uint32_t a[4], const uint32_t b[2]) {
    asm volatile(
        "mma.sync.aligned.m16n8k8.row.col.f32.tf32.tf32.f32 "
        "{%0,%1,%2,%3}, {%4,%5,%6,%7}, {%8,%9}, {%0,%1,%2,%3};\n"
        : "+f"(d.x), "+f"(d.y), "+f"(d.z), "+f"(d.w)
        : "r"(a[0]), "r"(a[1]), "r"(a[2]), "r"(a[3]), "r"(b[0]), "r"(b[1]));
}

// One CTA per window, 512 threads (16 warps), fully fused, all GEMMs on tensor
// cores (m16n8k8 tf32). Fragment row/col mapping: g = lane>>2, tg = lane&3.
//   A: a0(r=g, c=tg) a1(r=g+8, c=tg) a2(r=g, c=tg+4) a3(r=g+8, c=tg+4)
//   B: b0(k=tg, n=g) b1(k=tg+4, n=g)
//   C: c0(r=g, n=2tg) c1(r=g, n=2tg+1) c2/c3 rows +8
template <int BRANCH, int NTOK>
__global__ void __launch_bounds__(512, 1)
win_attn_mma(const float* __restrict__ x,
             const float* __restrict__ qkvw, const float* __restrict__ qkvb,
             const float* __restrict__ projw, const float* __restrict__ projb,
             float* __restrict__ out)
{
    extern __shared__ float sm[];
    uint32_t* smu = (uint32_t*)sm;
    int* tokidx = (int*)(sm + SMEM_FLOATS);

    const int t    = threadIdx.x;
    const int lane = t & 31;
    const int wrp  = t >> 5;        // 0..15
    const int g    = lane >> 2;
    const int tg   = lane & 3;
    const int win  = blockIdx.x;

    if (t < NTOK) tokidx[t] = tok_index<BRANCH>(win, t);

    // ---- x -> xa (tf32), pad rows zeroed ----
    for (int idx = t; idx < ROWS * 32; idx += 512) {
        int r = idx >> 5, c = (idx & 31) << 2;
        float4 v = make_float4(0.f, 0.f, 0.f, 0.f);
        if (r < NTOK)
            v = ((const float4*)x)[(size_t)tok_index<BRANCH>(win, r) * 32 + (c >> 2)];
        uint4 u = make_uint4(f2tf(v.x), f2tf(v.y), f2tf(v.z), f2tf(v.w));
        *(uint4*)&smu[OFF_X + r * S + c] = u;
    }
    __syncthreads();

    // Warp tiling for the two 128-col GEMMs: 2 m-tiles x 2 n-tiles per warp.
    const int mb = (wrp & 1) * 2;        // m-tile base
    const int n0 = (wrp >> 1) * 16;      // n columns [n0, n0+16)
    const float qscale = 0.1767766952966369f;  // 32^-0.5, folded into q

    // ---- QKV GEMM: X(64x128) @ Wqkv chunk(128x128), 3 chunks (q,k,v) ----
    #pragma unroll 1
    for (int cc = 0; cc < 3; cc++) {
        for (int idx = t; idx < 128 * 32; idx += 512) {
            int k = idx >> 5, c = (idx & 31) << 2;
            float4 wv = *(const float4*)&qkvw[k * 384 + cc * 128 + c];
            uint4 u = make_uint4(f2tf(wv.x), f2tf(wv.y), f2tf(wv.z), f2tf(wv.w));
            *(uint4*)&smu[OFF_RB + k * WS + c] = u;
        }
        __syncthreads();

        float4 acc[2][2];
        #pragma unroll
        for (int n = 0; n < 2; n++) {
            float b0 = qkvb[cc * 128 + n0 + n * 8 + 2 * tg];
            float b1 = qkvb[cc * 128 + n0 + n * 8 + 2 * tg + 1];
            acc[0][n] = make_float4(b0, b1, b0, b1);
            acc[1][n] = acc[0][n];
        }

        #pragma unroll 4
        for (int kt = 0; kt < 16; kt++) {
            int k0 = kt * 8;
            uint32_t a[2][4];
            #pragma unroll
            for (int m = 0; m < 2; m++) {
                int r = (mb + m) * 16 + g;
                a[m][0] = smu[OFF_X + r * S + k0 + tg];
                a[m][1] = smu[OFF_X + (r + 8) * S + k0 + tg];
                a[m][2] = smu[OFF_X + r * S + k0 + tg + 4];
                a[m][3] = smu[OFF_X + (r + 8) * S + k0 + tg + 4];
            }
            uint32_t b[2][2];
            #pragma unroll
            for (int n = 0; n < 2; n++) {
                b[n][0] = smu[OFF_RB + (k0 + tg) * WS + n0 + n * 8 + g];
                b[n][1] = smu[OFF_RB + (k0 + tg + 4) * WS + n0 + n * 8 + g];
            }
            #pragma unroll
            for (int m = 0; m < 2; m++)
                #pragma unroll
                for (int n = 0; n < 2; n++)
                    mma8(acc[m][n], a[m], b[n]);
        }

        const int dst = (cc == 0) ? OFF_Q : (cc == 1 ? OFF_K : OFF_V);
        const float mul = (cc == 0) ? qscale : 1.0f;
        #pragma unroll
        for (int m = 0; m < 2; m++) {
            int r = (mb + m) * 16 + g;
            #pragma unroll
            for (int n = 0; n < 2; n++) {
                int c = n0 + n * 8 + 2 * tg;
                *(uint2*)&smu[dst + r * S + c] =
                    make_uint2(f2tf(acc[m][n].x * mul), f2tf(acc[m][n].y * mul));
                *(uint2*)&smu[dst + (r + 8) * S + c] =
                    make_uint2(f2tf(acc[m][n].z * mul), f2tf(acc[m][n].w * mul));
            }
        }
        __syncthreads();
    }

    // ---- scores: per head, Q(64x32) @ K^T -> sc[h][i][j] (fp32) ----
    {
        const int h  = wrp >> 2;
        const int r0 = (wrp & 3) * 16 + g;
        float4 acc[7];
        #pragma unroll
        for (int n = 0; n < 7; n++) acc[n] = make_float4(0.f, 0.f, 0.f, 0.f);
        #pragma unroll
        for (int kt = 0; kt < 4; kt++) {
            int k0 = h * 32 + kt * 8;
            uint32_t a[4];
            a[0] = smu[OFF_Q + r0 * S + k0 + tg];
            a[1] = smu[OFF_Q + (r0 + 8) * S + k0 + tg];
            a[2] = smu[OFF_Q + r0 * S + k0 + tg + 4];
            a[3] = smu[OFF_Q + (r0 + 8) * S + k0 + tg + 4];
            #pragma unroll
            for (int n = 0; n < 7; n++) {
                uint32_t b[2];
                b[0] = smu[OFF_K + (n * 8 + g) * S + k0 + tg];
                b[1] = smu[OFF_K + (n * 8 + g) * S + k0 + tg + 4];
                mma8(acc[n], a, b);
            }
        }
        const int base = OFF_RB + (h * 64) * SCS;
        #pragma unroll
        for (int n = 0; n < 7; n++) {
            int j = n * 8 + 2 * tg;
            *(float2*)&sm[base + r0 * SCS + j] = make_float2(acc[n].x, acc[n].y);
            *(float2*)&sm[base + (r0 + 8) * SCS + j] = make_float2(acc[n].z, acc[n].w);
        }
    }
    __syncthreads();

    // Branch xy (NTOK=49): zero pad score columns so the attn@V k-loop
    // (7 tiles over j<56) multiplies the pad region by 0.
    if (NTOK < 56) {
        if (t < 256) {
            #pragma unroll
            for (int j = NTOK; j < 56; j++)
                sm[OFF_RB + t * SCS + j] = 0.f;
        }
        __syncthreads();
    }

    // ---- softmax over j (warp per row); write P as tf32 ----
    for (int row = wrp; row < 4 * NTOK; row += 16) {
        int h = row / NTOK, i = row - h * NTOK;
        float* sr = sm + OFF_RB + (h * 64 + i) * SCS;
        float v0 = sr[lane];                                      // lane < 32 <= NTOK
        float v1 = (lane + 32 < NTOK) ? sr[lane + 32] : -1e30f;
        float mx = fmaxf(v0, v1);
        #pragma unroll
        for (int o = 16; o; o >>= 1) mx = fmaxf(mx, __shfl_xor_sync(~0u, mx, o));
        float e0 = __expf(v0 - mx);
        float e1 = (lane + 32 < NTOK) ? __expf(v1 - mx) : 0.f;
        float ss = e0 + e1;
        #pragma unroll
        for (int o = 16; o; o >>= 1) ss += __shfl_xor_sync(~0u, ss, o);
        float inv = 1.0f / ss;
        sr[lane] = __uint_as_float(f2tf(e0 * inv));
        if (lane + 32 < NTOK) sr[lane + 32] = __uint_as_float(f2tf(e1 * inv));
    }
    __syncthreads();

    // ---- attn @ V -> xa ----
    {
        const int h  = wrp >> 2;
        const int r0 = (wrp & 3) * 16 + g;
        const int base = OFF_RB + (h * 64) * SCS;
        float4 acc[4];
        #pragma unroll
        for (int n = 0; n < 4; n++) acc[n] = make_float4(0.f, 0.f, 0.f, 0.f);
        #pragma unroll
        for (int kt = 0; kt < 7; kt++) {
            int k0 = kt * 8;
            uint32_t a[4];
            a[0] = smu[base + r0 * SCS + k0 + tg];
            a[1] = smu[base + (r0 + 8) * SCS + k0 + tg];
            a[2] = smu[base + r0 * SCS + k0 + tg + 4];
            a[3] = smu[base + (r0 + 8) * SCS + k0 + tg + 4];
            #pragma unroll
            for (int n = 0; n < 4; n++) {
                uint32_t b[2];
                b[0] = smu[OFF_V + (k0 + tg) * S + h * 32 + n * 8 + g];
                b[1] = smu[OFF_V + (k0 + tg + 4) * S + h * 32 + n * 8 + g];
                mma8(acc[n], a, b);
            }
        }
        #pragma unroll
        for (int n = 0; n < 4; n++) {
            int c = h * 32 + n * 8 + 2 * tg;
            *(uint2*)&smu[OFF_X + r0 * S + c] =
                make_uint2(f2tf(acc[n].x), f2tf(acc[n].y));
            *(uint2*)&smu[OFF_X + (r0 + 8) * S + c] =
                make_uint2(f2tf(acc[n].z), f2tf(acc[n].w));
        }
    }
    __syncthreads();

    // ---- proj GEMM: attnout(64x128) @ Wproj(128x128) -> global ----
    for (int idx = t; idx < 128 * 32; idx += 512) {
        int k = idx >> 5, c = (idx & 31) << 2;
        float4 wv = *(const float4*)&projw[k * 128 + c];
        uint4 u = make_uint4(f2tf(wv.x), f2tf(wv.y), f2tf(wv.z), f2tf(wv.w));
        *(uint4*)&smu[OFF_RB + k * WS + c] = u;
    }
    __syncthreads();
    {
        float4 acc[2][2];
        #pragma unroll
        for (int n = 0; n < 2; n++) {
            float b0 = projb[n0 + n * 8 + 2 * tg];
            float b1 = projb[n0 + n * 8 + 2 * tg + 1];
            acc[0][n] = make_float4(b0, b1, b0, b1);
            acc[1][n] = acc[0][n];
        }
        #pragma unroll 4
        for (int kt = 0; kt < 16; kt++) {
            int k0 = kt * 8;
            uint32_t a[2][4];
            #pragma unroll
            for (int m = 0; m < 2; m++) {
                int r = (mb + m) * 16 + g;
                a[m][0] = smu[OFF_X + r * S + k0 + tg];
                a[m][1] = smu[OFF_X + (r + 8) * S + k0 + tg];
                a[m][2] = smu[OFF_X + r * S + k0 + tg + 4];
                a[m][3] = smu[OFF_X + (r + 8) * S + k0 + tg + 4];
            }
            uint32_t b[2][2];
            #pragma unroll
            for (int n = 0; n < 2; n++) {
                b[n][0] = smu[OFF_RB + (k0 + tg) * WS + n0 + n * 8 + g];
                b[n][1] = smu[OFF_RB + (k0 + tg + 4) * WS + n0 + n * 8 + g];
            }
            #pragma unroll
            for (int m = 0; m < 2; m++)
                #pragma unroll
                for (int n = 0; n < 2; n++)
                    mma8(acc[m][n], a[m], b[n]);
        }

        #pragma unroll
        for (int m = 0; m < 2; m++) {
            #pragma unroll
            for (int rr = 0; rr < 2; rr++) {
                int r = (mb + m) * 16 + g + rr * 8;
                if (r < NTOK) {
                    #pragma unroll
                    for (int n = 0; n < 2; n++) {
                        float2 val = rr ? make_float2(acc[m][n].z, acc[m][n].w)
                                        : make_float2(acc[m][n].x, acc[m][n].y);
                        size_t o = (size_t)tokidx[r] * 128 + n0 + n * 8 + 2 * tg;
                        if (BRANCH != 0) {
                            float2 cur = *(const float2*)&out[o];
                            val.x += cur.x; val.y += cur.y;
                        }
                        *(float2*)&out[o] = val;
                    }
                }
            }
        }
    }
}

extern "C" void kernel_launch(void* const* d_in, const int* in_sizes, int n_in,
                              void* d_out, int out_size)
{
    const float* x         = (const float*)d_in[0];
    const float* qkv_w     = (const float*)d_in[1];
    const float* qkv_b     = (const float*)d_in[2];
    const float* qkv_th_w  = (const float*)d_in[3];
    const float* qkv_th_b  = (const float*)d_in[4];
    const float* qkv_tw_w  = (const float*)d_in[5];
    const float* qkv_tw_b  = (const float*)d_in[6];
    const float* proj_w    = (const float*)d_in[7];
    const float* proj_b    = (const float*)d_in[8];
    const float* proj_th_w = (const float*)d_in[9];
    const float* proj_th_b = (const float*)d_in[10];
    const float* proj_tw_w = (const float*)d_in[11];
    const float* proj_tw_b = (const float*)d_in[12];
    float* out = (float*)d_out;

    cudaFuncSetAttribute(win_attn_mma<0, 49>,
                         cudaFuncAttributeMaxDynamicSharedMemorySize, SMEM_BYTES);
    cudaFuncSetAttribute(win_attn_mma<1, 56>,
                         cudaFuncAttributeMaxDynamicSharedMemorySize, SMEM_BYTES);
    cudaFuncSetAttribute(win_attn_mma<2, 56>,
                         cudaFuncAttributeMaxDynamicSharedMemorySize, SMEM_BYTES);

    // xy writes every output exactly once; th / tw accumulate (same stream).
    win_attn_mma<0, 49><<<4096, 512, SMEM_BYTES>>>(
        x, qkv_w, qkv_b, proj_w, proj_b, out);
    win_attn_mma<1, 56><<<3584, 512, SMEM_BYTES>>>(
        x, qkv_th_w, qkv_th_b, proj_th_w, proj_th_b, out);
    win_attn_mma<2, 56><<<3584, 512, SMEM_BYTES>>>(
        x, qkv_tw_w, qkv_tw_b, proj_tw_w, proj_tw_b, out);
}

// round 4
// speedup vs baseline: 6.9894x; 1.7031x over previous
#include <cuda_runtime.h>
#include <cuda_fp16.h>
#include <cstdint>

// Problem constants: B=8, D=8, H=W=56, C=128, 4 heads x 32, windows (8,7,7),
// all pads zero. xy: 4096 windows x 49 tok; th/tw: 3584 x 56.
//
// All smem operands fp16 (same 10-bit mantissa as tf32), fp32 accumulate,
// mma.m16n8k16. Column layout within each 16-block is pair-permuted:
// stored position 4i..4i+3 holds logical cols (2i, 2i+1, 2i+8, 2i+9), so
// A-fragments are two LDS.64 and B-fragments one LDS.64 per mma.

static constexpr int SH   = 144;  // stride (halves) for X/Q/K rows
static constexpr int WSH  = 144;  // stride for staged weight rows
static constexpr int VSH  = 80;   // stride for VT rows
static constexpr int PSH  = 80;   // stride for P rows

static constexpr int OFF_X  = 0;                    // 64 x SH   (x input, later attn output)
static constexpr int OFF_Q  = OFF_X + 64 * SH;      // 64 x SH
static constexpr int OFF_K  = OFF_Q + 64 * SH;      // 64 x SH
static constexpr int OFF_VT = OFF_K + 64 * SH;      // 128 x VSH (V^T: row=channel, col=token-perm)
static constexpr int OFF_P  = OFF_VT + 128 * VSH;   // 4 heads x 64 x PSH
static constexpr int OFF_W  = OFF_P + 4 * 64 * PSH; // 128 x WSH (staged weight chunk)
static constexpr int TOT_HALVES = OFF_W + 128 * WSH;
static constexpr int SMEM_BYTES = TOT_HALVES * 2 + 64 * 4;     // + tokidx

// Pre-converted fp16 weights, transposed (row = output col n, col = k perm).
__device__ __align__(16) __half g_qkvwt[3][384 * 128];
__device__ __align__(16) __half g_projwt[3][128 * 128];

template <int BRANCH>
__device__ __forceinline__ int tok_index(int win, int tt) {
    if (BRANCH == 0) {                 // xy: (b, d, hb, wb) x (hh, ww)
        int b  = win >> 9;
        int d  = (win >> 6) & 7;
        int hb = (win >> 3) & 7;
        int wb = win & 7;
        int hh = tt / 7, wq = tt - hh * 7;
        return ((b * 8 + d) * 56 + hb * 7 + hh) * 56 + wb * 7 + wq;
    } else if (BRANCH == 1) {          // th: (b, hb, w) x (dd, hh)
        int b  = win / 448;
        int r  = win - b * 448;
        int hb = r / 56;
        int w  = r - hb * 56;
        int dd = tt / 7, hh = tt - dd * 7;
        return ((b * 8 + dd) * 56 + hb * 7 + hh) * 56 + w;
    } else {                           // tw: (b, h, wb) x (dd, ww)
        int b  = win / 448;
        int r  = win - b * 448;
        int h  = r >> 3;
        int wb = r & 7;
        int dd = tt / 7, wq = tt - dd * 7;
        return ((b * 8 + dd) * 56 + h) * 56 + wb * 7 + wq;
    }
}

// D += A(16x16) * B(16x8), f16 in, f32 accumulate.
__device__ __forceinline__ void mma16(float4& d, uint32_t a0, uint32_t a1,
                                      uint32_t a2, uint32_t a3,
                                      uint32_t b0, uint32_t b1) {
    asm volatile(
        "mma.sync.aligned.m16n8k16.row.col.f32.f16.f16.f32 "
        "{%0,%1,%2,%3}, {%4,%5,%6,%7}, {%8,%9}, {%0,%1,%2,%3};\n"
        : "+f"(d.x), "+f"(d.y), "+f"(d.z), "+f"(d.w)
        : "r"(a0), "r"(a1), "r"(a2), "r"(a3), "r"(b0), "r"(b1));
}

// Permuted position of logical column r16 within its 16-block.
__device__ __forceinline__ int vpos(int r) {
    int rb = r >> 4, r16 = r & 15;
    return rb * 16 + ((r16 & 7) >> 1) * 4 + (r16 & 1) + ((r16 & 8) ? 2 : 0);
}

__device__ __forceinline__ uint32_t h2u(float a, float b) {
    __half2 h = __floats2half2_rn(a, b);
    return *(uint32_t*)&h;
}

// ---------------- weight pre-conversion (runs once per launch) ----------------
__global__ void conv_weights(const float* __restrict__ w0, const float* __restrict__ w1,
                             const float* __restrict__ w2, const float* __restrict__ p0,
                             const float* __restrict__ p1, const float* __restrict__ p2) {
    int tid = blockIdx.x * 256 + threadIdx.x;
    const int QK = 3 * 384 * 128;
    if (tid < QK) {
        int br  = tid / (384 * 128);
        int rem = tid - br * 384 * 128;
        int n = rem >> 7, kp = rem & 127;
        int b = kp >> 4, p = kp & 15;
        int k = b * 16 + ((p >> 2) * 2) + (p & 1) + ((p & 2) ? 8 : 0);
        const float* src = (br == 0) ? w0 : (br == 1 ? w1 : w2);
        g_qkvwt[br][rem] = __float2half_rn(src[k * 384 + n]);
    } else {
        int t2  = tid - QK;
        int br  = t2 / (128 * 128);
        int rem = t2 - br * 16384;
        int n = rem >> 7, kp = rem & 127;
        int b = kp >> 4, p = kp & 15;
        int k = b * 16 + ((p >> 2) * 2) + (p & 1) + ((p & 2) ? 8 : 0);
        const float* src = (br == 0) ? p0 : (br == 1 ? p1 : p2);
        g_projwt[br][rem] = __float2half_rn(src[k * 128 + n]);
    }
}

// ---------------- fused window attention, one CTA per window ----------------
template <int BRANCH, int NTOK>
__global__ void __launch_bounds__(512, 1)
win_attn_h(const float* __restrict__ x,
           const float* __restrict__ qkvb, const float* __restrict__ projb,
           float* __restrict__ out)
{
    extern __shared__ __align__(16) __half smh[];
    int* tokidx = (int*)(smh + TOT_HALVES);

    const int t    = threadIdx.x;
    const int lane = t & 31;
    const int wrp  = t >> 5;        // 0..15
    const int g    = lane >> 2;
    const int tg   = lane & 3;
    const int win  = blockIdx.x;

    if (t < NTOK) tokidx[t] = tok_index<BRANCH>(win, t);

    // ---- x -> X (fp16, permuted), pad rows zeroed ----
    // 128 halves per row = 32 uint2 chunks.  (R3 bug: extent was 64*16.)
    for (int idx = t; idx < 64 * 32; idx += 512) {
        int r = idx >> 5, q = idx & 31;
        int b = q >> 2, i = q & 3;
        uint2 u = make_uint2(0u, 0u);
        if (r < NTOK) {
            const float* row = x + (size_t)tok_index<BRANCH>(win, r) * 128 + b * 16 + 2 * i;
            float2 lo = *(const float2*)row;        // cols 2i, 2i+1
            float2 hi = *(const float2*)(row + 8);  // cols 2i+8, 2i+9
            u.x = h2u(lo.x, lo.y);
            u.y = h2u(hi.x, hi.y);
        }
        *(uint2*)&smh[OFF_X + r * SH + q * 4] = u;
    }
    __syncthreads();

    const int mb = (wrp & 1) * 2;        // m-tiles {mb, mb+1}
    const int n0 = (wrp >> 1) * 16;      // n columns [n0, n0+16)
    const float qscale = 0.1767766952966369f;

    // ---- QKV GEMM: X(64x128) @ W chunk(128x128), chunks q,k,v ----
    #pragma unroll 1
    for (int cc = 0; cc < 3; cc++) {
        const __half* wsrc = g_qkvwt[BRANCH] + cc * 128 * 128;
        for (int idx = t; idx < 128 * 16; idx += 512) {
            int rw = idx >> 4, c8 = idx & 15;
            *(uint4*)&smh[OFF_W + rw * WSH + c8 * 8] = *(const uint4*)&wsrc[rw * 128 + c8 * 8];
        }
        __syncthreads();

        float4 acc[2][2];
        #pragma unroll
        for (int n = 0; n < 2; n++) {
            float b0 = qkvb[cc * 128 + n0 + n * 8 + 2 * tg];
            float b1 = qkvb[cc * 128 + n0 + n * 8 + 2 * tg + 1];
            acc[0][n] = make_float4(b0, b1, b0, b1);
            acc[1][n] = acc[0][n];
        }

        #pragma unroll 4
        for (int kt = 0; kt < 8; kt++) {
            int kb = kt * 16;
            uint2 A[2][2];
            #pragma unroll
            for (int m = 0; m < 2; m++) {
                int r = (mb + m) * 16 + g;
                A[m][0] = *(const uint2*)&smh[OFF_X + r * SH + kb + 4 * tg];
                A[m][1] = *(const uint2*)&smh[OFF_X + (r + 8) * SH + kb + 4 * tg];
            }
            uint2 B[2];
            #pragma unroll
            for (int n = 0; n < 2; n++) {
                int nn = n0 + n * 8 + g;
                B[n] = *(const uint2*)&smh[OFF_W + nn * WSH + kb + 4 * tg];
            }
            #pragma unroll
            for (int m = 0; m < 2; m++)
                #pragma unroll
                for (int n = 0; n < 2; n++)
                    mma16(acc[m][n], A[m][0].x, A[m][1].x, A[m][0].y, A[m][1].y,
                          B[n].x, B[n].y);
        }

        if (cc < 2) {   // q or k: activation layout, permuted half2 stores
            const int dst = (cc == 0) ? OFF_Q : OFF_K;
            const float mul = (cc == 0) ? qscale : 1.0f;
            #pragma unroll
            for (int m = 0; m < 2; m++) {
                int r = (mb + m) * 16 + g;
                #pragma unroll
                for (int n = 0; n < 2; n++) {
                    int pos = n0 + 4 * tg + 2 * n;   // perm of col n0+n*8+2tg
                    *(uint32_t*)&smh[dst + r * SH + pos] =
                        h2u(acc[m][n].x * mul, acc[m][n].y * mul);
                    *(uint32_t*)&smh[dst + (r + 8) * SH + pos] =
                        h2u(acc[m][n].z * mul, acc[m][n].w * mul);
                }
            }
        } else {        // v: transposed into VT[channel][token-perm]
            #pragma unroll
            for (int m = 0; m < 2; m++) {
                int r = (mb + m) * 16 + g, r2 = r + 8;
                #pragma unroll
                for (int n = 0; n < 2; n++) {
                    int c = n0 + n * 8 + 2 * tg;
                    smh[OFF_VT + c * VSH + vpos(r)]        = __float2half_rn(acc[m][n].x);
                    smh[OFF_VT + (c + 1) * VSH + vpos(r)]  = __float2half_rn(acc[m][n].y);
                    smh[OFF_VT + c * VSH + vpos(r2)]       = __float2half_rn(acc[m][n].z);
                    smh[OFF_VT + (c + 1) * VSH + vpos(r2)] = __float2half_rn(acc[m][n].w);
                }
            }
        }
        __syncthreads();
    }

    // Prefetch proj weights into OFF_W (overlaps with scores/attn compute).
    {
        const __half* psrc = g_projwt[BRANCH];
        for (int idx = t; idx < 128 * 16; idx += 512) {
            int rw = idx >> 4, c8 = idx & 15;
            *(uint4*)&smh[OFF_W + rw * WSH + c8 * 8] = *(const uint4*)&psrc[rw * 128 + c8 * 8];
        }
    }

    // ---- scores: warp (h, mt) computes rows mt*16+{g,g+8}, all j ----
    const int h  = wrp >> 2;
    const int mt = wrp & 3;
    const int r0 = mt * 16 + g;
    {
        float4 sacc[7];
        #pragma unroll
        for (int n = 0; n < 7; n++) sacc[n] = make_float4(0.f, 0.f, 0.f, 0.f);
        #pragma unroll
        for (int kt = 0; kt < 2; kt++) {
            int kb = h * 32 + kt * 16;
            uint2 A0 = *(const uint2*)&smh[OFF_Q + r0 * SH + kb + 4 * tg];
            uint2 A1 = *(const uint2*)&smh[OFF_Q + (r0 + 8) * SH + kb + 4 * tg];
            #pragma unroll
            for (int n = 0; n < 7; n++) {
                uint2 Bn = *(const uint2*)&smh[OFF_K + (n * 8 + g) * SH + kb + 4 * tg];
                mma16(sacc[n], A0.x, A1.x, A0.y, A1.y, Bn.x, Bn.y);
            }
        }

        // register softmax: rows r0 (x,y) and r0+8 (z,w) live in this lane-quad
        if (NTOK < 56) {
            #pragma unroll
            for (int n = 0; n < 7; n++) {
                int j0 = 8 * n + 2 * tg;
                if (j0 >= NTOK)     { sacc[n].x = -1e30f; sacc[n].z = -1e30f; }
                if (j0 + 1 >= NTOK) { sacc[n].y = -1e30f; sacc[n].w = -1e30f; }
            }
        }
        float mA = -1e30f, mB = -1e30f;
        #pragma unroll
        for (int n = 0; n < 7; n++) {
            mA = fmaxf(mA, fmaxf(sacc[n].x, sacc[n].y));
            mB = fmaxf(mB, fmaxf(sacc[n].z, sacc[n].w));
        }
        #pragma unroll
        for (int o = 1; o <= 2; o <<= 1) {
            mA = fmaxf(mA, __shfl_xor_sync(~0u, mA, o));
            mB = fmaxf(mB, __shfl_xor_sync(~0u, mB, o));
        }
        float sA = 0.f, sB = 0.f;
        #pragma unroll
        for (int n = 0; n < 7; n++) {
            sacc[n].x = __expf(sacc[n].x - mA);
            sacc[n].y = __expf(sacc[n].y - mA);
            sacc[n].z = __expf(sacc[n].z - mB);
            sacc[n].w = __expf(sacc[n].w - mB);
            sA += sacc[n].x + sacc[n].y;
            sB += sacc[n].z + sacc[n].w;
        }
        #pragma unroll
        for (int o = 1; o <= 2; o <<= 1) {
            sA += __shfl_xor_sync(~0u, sA, o);
            sB += __shfl_xor_sync(~0u, sB, o);
        }
        float iA = 1.0f / sA, iB = 1.0f / sB;

        // store P (fp16, A-fragment layout); zero pad j = 56..63
        const int pb = OFF_P + (h * 64) * PSH;
        #pragma unroll
        for (int n = 0; n < 7; n++) {
            int pos = (n >> 1) * 16 + 4 * tg + 2 * (n & 1);
            *(uint32_t*)&smh[pb + r0 * PSH + pos]       = h2u(sacc[n].x * iA, sacc[n].y * iA);
            *(uint32_t*)&smh[pb + (r0 + 8) * PSH + pos] = h2u(sacc[n].z * iB, sacc[n].w * iB);
        }
        *(uint32_t*)&smh[pb + r0 * PSH + 48 + 4 * tg + 2]       = 0u;
        *(uint32_t*)&smh[pb + (r0 + 8) * PSH + 48 + 4 * tg + 2] = 0u;
    }
    __syncwarp();   // P rows are warp-private (each lane re-reads only its own data)

    // ---- attn @ V -> X region (fp16, activation layout) ----
    {
        const int pb = OFF_P + (h * 64) * PSH;
        float4 vacc[4];
        #pragma unroll
        for (int n = 0; n < 4; n++) vacc[n] = make_float4(0.f, 0.f, 0.f, 0.f);
        #pragma unroll
        for (int kt = 0; kt < 4; kt++) {
            int kb = kt * 16;
            uint2 A0 = *(const uint2*)&smh[pb + r0 * PSH + kb + 4 * tg];
            uint2 A1 = *(const uint2*)&smh[pb + (r0 + 8) * PSH + kb + 4 * tg];
            #pragma unroll
            for (int n = 0; n < 4; n++) {
                int c = h * 32 + n * 8 + g;
                uint2 Bn = *(const uint2*)&smh[OFF_VT + c * VSH + kb + 4 * tg];
                mma16(vacc[n], A0.x, A1.x, A0.y, A1.y, Bn.x, Bn.y);
            }
        }
        #pragma unroll
        for (int n = 0; n < 4; n++) {
            int pos = h * 32 + (n >> 1) * 16 + 4 * tg + 2 * (n & 1);
            *(uint32_t*)&smh[OFF_X + r0 * SH + pos]       = h2u(vacc[n].x, vacc[n].y);
            *(uint32_t*)&smh[OFF_X + (r0 + 8) * SH + pos] = h2u(vacc[n].z, vacc[n].w);
        }
    }
    __syncthreads();

    // ---- proj GEMM: attnout(64x128) @ Wproj(128x128) -> global ----
    {
        float4 acc[2][2];
        #pragma unroll
        for (int n = 0; n < 2; n++) {
            float b0 = projb[n0 + n * 8 + 2 * tg];
            float b1 = projb[n0 + n * 8 + 2 * tg + 1];
            acc[0][n] = make_float4(b0, b1, b0, b1);
            acc[1][n] = acc[0][n];
        }
        #pragma unroll 4
        for (int kt = 0; kt < 8; kt++) {
            int kb = kt * 16;
            uint2 A[2][2];
            #pragma unroll
            for (int m = 0; m < 2; m++) {
                int r = (mb + m) * 16 + g;
                A[m][0] = *(const uint2*)&smh[OFF_X + r * SH + kb + 4 * tg];
                A[m][1] = *(const uint2*)&smh[OFF_X + (r + 8) * SH + kb + 4 * tg];
            }
            uint2 B[2];
            #pragma unroll
            for (int n = 0; n < 2; n++) {
                int nn = n0 + n * 8 + g;
                B[n] = *(const uint2*)&smh[OFF_W + nn * WSH + kb + 4 * tg];
            }
            #pragma unroll
            for (int m = 0; m < 2; m++)
                #pragma unroll
                for (int n = 0; n < 2; n++)
                    mma16(acc[m][n], A[m][0].x, A[m][1].x, A[m][0].y, A[m][1].y,
                          B[n].x, B[n].y);
        }

        #pragma unroll
        for (int m = 0; m < 2; m++) {
            #pragma unroll
            for (int rr = 0; rr < 2; rr++) {
                int r = (mb + m) * 16 + g + rr * 8;
                if (r < NTOK) {
                    #pragma unroll
                    for (int n = 0; n < 2; n++) {
                        float2 val = rr ? make_float2(acc[m][n].z, acc[m][n].w)
                                        : make_float2(acc[m][n].x, acc[m][n].y);
                        size_t o = (size_t)tokidx[r] * 128 + n0 + n * 8 + 2 * tg;
                        if (BRANCH != 0) {
                            float2 cur = *(const float2*)&out[o];
                            val.x += cur.x; val.y += cur.y;
                        }
                        *(float2*)&out[o] = val;
                    }
                }
            }
        }
    }
}

extern "C" void kernel_launch(void* const* d_in, const int* in_sizes, int n_in,
                              void* d_out, int out_size)
{
    const float* x         = (const float*)d_in[0];
    const float* qkv_w     = (const float*)d_in[1];
    const float* qkv_b     = (const float*)d_in[2];
    const float* qkv_th_w  = (const float*)d_in[3];
    const float* qkv_th_b  = (const float*)d_in[4];
    const float* qkv_tw_w  = (const float*)d_in[5];
    const float* qkv_tw_b  = (const float*)d_in[6];
    const float* proj_w    = (const float*)d_in[7];
    const float* proj_b    = (const float*)d_in[8];
    const float* proj_th_w = (const float*)d_in[9];
    const float* proj_th_b = (const float*)d_in[10];
    const float* proj_tw_w = (const float*)d_in[11];
    const float* proj_tw_b = (const float*)d_in[12];
    float* out = (float*)d_out;

    conv_weights<<<768, 256>>>(qkv_w, qkv_th_w, qkv_tw_w,
                               proj_w, proj_th_w, proj_tw_w);

    cudaFuncSetAttribute(win_attn_h<0, 49>,
                         cudaFuncAttributeMaxDynamicSharedMemorySize, SMEM_BYTES);
    cudaFuncSetAttribute(win_attn_h<1, 56>,
                         cudaFuncAttributeMaxDynamicSharedMemorySize, SMEM_BYTES);
    cudaFuncSetAttribute(win_attn_h<2, 56>,
                         cudaFuncAttributeMaxDynamicSharedMemorySize, SMEM_BYTES);

    // xy writes every output exactly once; th / tw accumulate (same stream).
    win_attn_h<0, 49><<<4096, 512, SMEM_BYTES>>>(x, qkv_b, proj_b, out);
    win_attn_h<1, 56><<<3584, 512, SMEM_BYTES>>>(x, qkv_th_b, proj_th_b, out);
    win_attn_h<2, 56><<<3584, 512, SMEM_BYTES>>>(x, qkv_tw_b, proj_tw_b, out);
}

// round 5
// speedup vs baseline: 10.7861x; 1.5432x over previous
#include <cuda_runtime.h>
#include <cuda_fp16.h>
#include <cstdint>

// Problem constants: B=8, D=8, H=W=56, C=128, 4 heads x 32, windows (8,7,7),
// all pads zero. xy: 4096 windows x 49 tok; th/tw: 3584 x 56.
//
// fp16 storage (same mantissa as tf32), fp32 accumulate, mma.m16n8k16.
// Pair-permuted column layout: stored pos 4i..4i+3 = logical cols
// (2i, 2i+1, 2i+8, 2i+9) -> A frags are 2x LDS.64, B frags 1x LDS.64.
// P (softmax probs) is register-resident: scores C-fragment == PV A-fragment.

static constexpr int SH   = 144;  // stride (halves) for X/Q/K rows
static constexpr int WSH  = 144;  // stride for staged weight rows
static constexpr int VSH  = 80;   // stride for VT rows

static constexpr int OFF_X  = 0;                    // 64 x SH  (x, later attn output)
static constexpr int OFF_Q  = OFF_X + 64 * SH;      // 64 x SH
static constexpr int OFF_K  = OFF_Q + 64 * SH;      // 64 x SH
static constexpr int OFF_VT = OFF_K + 64 * SH;      // 128 x VSH (V^T: row=channel)
static constexpr int OFF_W  = OFF_VT + 128 * VSH;   // 128 x WSH (staged weights)
static constexpr int TOT_HALVES = OFF_W + 128 * WSH;           // 56320
static constexpr int SMEM_BYTES = TOT_HALVES * 2 + 64 * 4;     // 112896 -> 2 CTAs/SM

// Pre-converted fp16 weights, transposed (row = output col n, col = k perm).
__device__ __align__(16) __half g_qkvwt[3][384 * 128];
__device__ __align__(16) __half g_projwt[3][128 * 128];

template <int BRANCH>
__device__ __forceinline__ int tok_index(int win, int tt) {
    if (BRANCH == 0) {                 // xy: (b, d, hb, wb) x (hh, ww)
        int b  = win >> 9;
        int d  = (win >> 6) & 7;
        int hb = (win >> 3) & 7;
        int wb = win & 7;
        int hh = tt / 7, wq = tt - hh * 7;
        return ((b * 8 + d) * 56 + hb * 7 + hh) * 56 + wb * 7 + wq;
    } else if (BRANCH == 1) {          // th: (b, hb, w) x (dd, hh)
        int b  = win / 448;
        int r  = win - b * 448;
        int hb = r / 56;
        int w  = r - hb * 56;
        int dd = tt / 7, hh = tt - dd * 7;
        return ((b * 8 + dd) * 56 + hb * 7 + hh) * 56 + w;
    } else {                           // tw: (b, h, wb) x (dd, ww)
        int b  = win / 448;
        int r  = win - b * 448;
        int h  = r >> 3;
        int wb = r & 7;
        int dd = tt / 7, wq = tt - dd * 7;
        return ((b * 8 + dd) * 56 + h) * 56 + wb * 7 + wq;
    }
}

// D += A(16x16) * B(16x8), f16 in, f32 accumulate.
__device__ __forceinline__ void mma16(float4& d, uint32_t a0, uint32_t a1,
                                      uint32_t a2, uint32_t a3,
                                      uint32_t b0, uint32_t b1) {
    asm volatile(
        "mma.sync.aligned.m16n8k16.row.col.f32.f16.f16.f32 "
        "{%0,%1,%2,%3}, {%4,%5,%6,%7}, {%8,%9}, {%0,%1,%2,%3};\n"
        : "+f"(d.x), "+f"(d.y), "+f"(d.z), "+f"(d.w)
        : "r"(a0), "r"(a1), "r"(a2), "r"(a3), "r"(b0), "r"(b1));
}

// Permuted position of logical column r16 within its 16-block.
__device__ __forceinline__ int vpos(int r) {
    int rb = r >> 4, r16 = r & 15;
    return rb * 16 + ((r16 & 7) >> 1) * 4 + (r16 & 1) + ((r16 & 8) ? 2 : 0);
}

__device__ __forceinline__ uint32_t h2u(float a, float b) {
    __half2 h = __floats2half2_rn(a, b);
    return *(uint32_t*)&h;
}

// ---------------- weight pre-conversion (runs once per launch) ----------------
__global__ void conv_weights(const float* __restrict__ w0, const float* __restrict__ w1,
                             const float* __restrict__ w2, const float* __restrict__ p0,
                             const float* __restrict__ p1, const float* __restrict__ p2) {
    int tid = blockIdx.x * 256 + threadIdx.x;
    const int QK = 3 * 384 * 128;
    if (tid < QK) {
        int br  = tid / (384 * 128);
        int rem = tid - br * 384 * 128;
        int n = rem >> 7, kp = rem & 127;
        int b = kp >> 4, p = kp & 15;
        int k = b * 16 + ((p >> 2) * 2) + (p & 1) + ((p & 2) ? 8 : 0);
        const float* src = (br == 0) ? w0 : (br == 1 ? w1 : w2);
        g_qkvwt[br][rem] = __float2half_rn(src[k * 384 + n]);
    } else {
        int t2  = tid - QK;
        int br  = t2 / (128 * 128);
        int rem = t2 - br * 16384;
        int n = rem >> 7, kp = rem & 127;
        int b = kp >> 4, p = kp & 15;
        int k = b * 16 + ((p >> 2) * 2) + (p & 1) + ((p & 2) ? 8 : 0);
        const float* src = (br == 0) ? p0 : (br == 1 ? p1 : p2);
        g_projwt[br][rem] = __float2half_rn(src[k * 128 + n]);
    }
}

// ---------------- fused window attention, one CTA per window ----------------
template <int BRANCH, int NTOK>
__global__ void __launch_bounds__(512, 2)
win_attn_h(const float* __restrict__ x,
           const float* __restrict__ qkvb, const float* __restrict__ projb,
           float* __restrict__ out)
{
    extern __shared__ __align__(16) __half smh[];
    int* tokidx = (int*)(smh + TOT_HALVES);

    const int t    = threadIdx.x;
    const int lane = t & 31;
    const int wrp  = t >> 5;        // 0..15
    const int g    = lane >> 2;
    const int tg   = lane & 3;
    const int win  = blockIdx.x;

    if (t < NTOK) tokidx[t] = tok_index<BRANCH>(win, t);

    // ---- x -> X (fp16, permuted), pad rows zeroed. 32 uint2 chunks/row ----
    for (int idx = t; idx < 64 * 32; idx += 512) {
        int r = idx >> 5, q = idx & 31;
        int b = q >> 2, i = q & 3;
        uint2 u = make_uint2(0u, 0u);
        if (r < NTOK) {
            const float* row = x + (size_t)tok_index<BRANCH>(win, r) * 128 + b * 16 + 2 * i;
            float2 lo = *(const float2*)row;        // cols 2i, 2i+1
            float2 hi = *(const float2*)(row + 8);  // cols 2i+8, 2i+9
            u.x = h2u(lo.x, lo.y);
            u.y = h2u(hi.x, hi.y);
        }
        *(uint2*)&smh[OFF_X + r * SH + q * 4] = u;
    }
    __syncthreads();

    const int mb = (wrp & 1) * 2;        // m-tiles {mb, mb+1}
    const int n0 = (wrp >> 1) * 16;      // n columns [n0, n0+16)
    const float qscale = 0.1767766952966369f;

    // ---- QKV GEMM: X(64x128) @ W chunk(128x128), chunks q,k,v ----
    #pragma unroll 1
    for (int cc = 0; cc < 3; cc++) {
        const __half* wsrc = g_qkvwt[BRANCH] + cc * 128 * 128;
        for (int idx = t; idx < 128 * 16; idx += 512) {
            int rw = idx >> 4, c8 = idx & 15;
            *(uint4*)&smh[OFF_W + rw * WSH + c8 * 8] = *(const uint4*)&wsrc[rw * 128 + c8 * 8];
        }
        __syncthreads();

        float4 acc[2][2];
        #pragma unroll
        for (int n = 0; n < 2; n++) {
            float b0 = qkvb[cc * 128 + n0 + n * 8 + 2 * tg];
            float b1 = qkvb[cc * 128 + n0 + n * 8 + 2 * tg + 1];
            acc[0][n] = make_float4(b0, b1, b0, b1);
            acc[1][n] = acc[0][n];
        }

        #pragma unroll 4
        for (int kt = 0; kt < 8; kt++) {
            int kb = kt * 16;
            uint2 A[2][2];
            #pragma unroll
            for (int m = 0; m < 2; m++) {
                int r = (mb + m) * 16 + g;
                A[m][0] = *(const uint2*)&smh[OFF_X + r * SH + kb + 4 * tg];
                A[m][1] = *(const uint2*)&smh[OFF_X + (r + 8) * SH + kb + 4 * tg];
            }
            uint2 B[2];
            #pragma unroll
            for (int n = 0; n < 2; n++) {
                int nn = n0 + n * 8 + g;
                B[n] = *(const uint2*)&smh[OFF_W + nn * WSH + kb + 4 * tg];
            }
            #pragma unroll
            for (int m = 0; m < 2; m++)
                #pragma unroll
                for (int n = 0; n < 2; n++)
                    mma16(acc[m][n], A[m][0].x, A[m][1].x, A[m][0].y, A[m][1].y,
                          B[n].x, B[n].y);
        }

        if (cc < 2) {   // q or k: activation layout, permuted half2 stores
            const int dst = (cc == 0) ? OFF_Q : OFF_K;
            const float mul = (cc == 0) ? qscale : 1.0f;
            #pragma unroll
            for (int m = 0; m < 2; m++) {
                int r = (mb + m) * 16 + g;
                #pragma unroll
                for (int n = 0; n < 2; n++) {
                    int pos = n0 + 4 * tg + 2 * n;   // perm of col n0+n*8+2tg
                    *(uint32_t*)&smh[dst + r * SH + pos] =
                        h2u(acc[m][n].x * mul, acc[m][n].y * mul);
                    *(uint32_t*)&smh[dst + (r + 8) * SH + pos] =
                        h2u(acc[m][n].z * mul, acc[m][n].w * mul);
                }
            }
        } else {        // v: transposed into VT[channel][token-perm]
            #pragma unroll
            for (int m = 0; m < 2; m++) {
                int r = (mb + m) * 16 + g, r2 = r + 8;
                #pragma unroll
                for (int n = 0; n < 2; n++) {
                    int c = n0 + n * 8 + 2 * tg;
                    smh[OFF_VT + c * VSH + vpos(r)]        = __float2half_rn(acc[m][n].x);
                    smh[OFF_VT + (c + 1) * VSH + vpos(r)]  = __float2half_rn(acc[m][n].y);
                    smh[OFF_VT + c * VSH + vpos(r2)]       = __float2half_rn(acc[m][n].z);
                    smh[OFF_VT + (c + 1) * VSH + vpos(r2)] = __float2half_rn(acc[m][n].w);
                }
            }
        }
        __syncthreads();
    }

    // Prefetch proj weights into OFF_W (overlaps with scores/attn compute).
    {
        const __half* psrc = g_projwt[BRANCH];
        for (int idx = t; idx < 128 * 16; idx += 512) {
            int rw = idx >> 4, c8 = idx & 15;
            *(uint4*)&smh[OFF_W + rw * WSH + c8 * 8] = *(const uint4*)&psrc[rw * 128 + c8 * 8];
        }
    }

    // ---- scores + softmax + P@V, P fully register-resident ----
    const int h  = wrp >> 2;
    const int mt = wrp & 3;
    const int r0 = mt * 16 + g;
    {
        float4 sacc[7];
        #pragma unroll
        for (int n = 0; n < 7; n++) sacc[n] = make_float4(0.f, 0.f, 0.f, 0.f);
        #pragma unroll
        for (int kt = 0; kt < 2; kt++) {
            int kb = h * 32 + kt * 16;
            uint2 A0 = *(const uint2*)&smh[OFF_Q + r0 * SH + kb + 4 * tg];
            uint2 A1 = *(const uint2*)&smh[OFF_Q + (r0 + 8) * SH + kb + 4 * tg];
            #pragma unroll
            for (int n = 0; n < 7; n++) {
                uint2 Bn = *(const uint2*)&smh[OFF_K + (n * 8 + g) * SH + kb + 4 * tg];
                mma16(sacc[n], A0.x, A1.x, A0.y, A1.y, Bn.x, Bn.y);
            }
        }

        // register softmax over j; rows r0 (x,y) and r0+8 (z,w) live in lane quad
        if (NTOK < 56) {
            #pragma unroll
            for (int n = 0; n < 7; n++) {
                int j0 = 8 * n + 2 * tg;
                if (j0 >= NTOK)     { sacc[n].x = -1e30f; sacc[n].z = -1e30f; }
                if (j0 + 1 >= NTOK) { sacc[n].y = -1e30f; sacc[n].w = -1e30f; }
            }
        }
        float mA = -1e30f, mB = -1e30f;
        #pragma unroll
        for (int n = 0; n < 7; n++) {
            mA = fmaxf(mA, fmaxf(sacc[n].x, sacc[n].y));
            mB = fmaxf(mB, fmaxf(sacc[n].z, sacc[n].w));
        }
        #pragma unroll
        for (int o = 1; o <= 2; o <<= 1) {
            mA = fmaxf(mA, __shfl_xor_sync(~0u, mA, o));
            mB = fmaxf(mB, __shfl_xor_sync(~0u, mB, o));
        }
        float sA = 0.f, sB = 0.f;
        #pragma unroll
        for (int n = 0; n < 7; n++) {
            sacc[n].x = __expf(sacc[n].x - mA);
            sacc[n].y = __expf(sacc[n].y - mA);
            sacc[n].z = __expf(sacc[n].z - mB);
            sacc[n].w = __expf(sacc[n].w - mB);
            sA += sacc[n].x + sacc[n].y;
            sB += sacc[n].z + sacc[n].w;
        }
        #pragma unroll
        for (int o = 1; o <= 2; o <<= 1) {
            sA += __shfl_xor_sync(~0u, sA, o);
            sB += __shfl_xor_sync(~0u, sB, o);
        }
        float iA = 1.0f / sA, iB = 1.0f / sB;

        // Pack P directly into PV A-fragment registers (scores C-frag layout
        // {S[r0][8n+2tg..], S[r0+8][..]} == A-frag {a(r0), a(r0+8)} per k-block).
        uint32_t pA[7], pB[7];
        #pragma unroll
        for (int n = 0; n < 7; n++) {
            pA[n] = h2u(sacc[n].x * iA, sacc[n].y * iA);
            pB[n] = h2u(sacc[n].z * iB, sacc[n].w * iB);
        }

        // ---- attn @ V -> X region (fp16, activation layout) ----
        float4 vacc[4];
        #pragma unroll
        for (int n = 0; n < 4; n++) vacc[n] = make_float4(0.f, 0.f, 0.f, 0.f);
        #pragma unroll
        for (int kt = 0; kt < 4; kt++) {
            int kb = kt * 16;
            uint32_t a0 = pA[2 * kt], a1 = pB[2 * kt];
            uint32_t a2 = (2 * kt + 1 < 7) ? pA[2 * kt + 1] : 0u;  // j=56..63 pad = 0
            uint32_t a3 = (2 * kt + 1 < 7) ? pB[2 * kt + 1] : 0u;
            #pragma unroll
            for (int n = 0; n < 4; n++) {
                int c = h * 32 + n * 8 + g;
                uint2 Bn = *(const uint2*)&smh[OFF_VT + c * VSH + kb + 4 * tg];
                mma16(vacc[n], a0, a1, a2, a3, Bn.x, Bn.y);
            }
        }
        #pragma unroll
        for (int n = 0; n < 4; n++) {
            int pos = h * 32 + (n >> 1) * 16 + 4 * tg + 2 * (n & 1);
            *(uint32_t*)&smh[OFF_X + r0 * SH + pos]       = h2u(vacc[n].x, vacc[n].y);
            *(uint32_t*)&smh[OFF_X + (r0 + 8) * SH + pos] = h2u(vacc[n].z, vacc[n].w);
        }
    }
    __syncthreads();

    // ---- proj GEMM: attnout(64x128) @ Wproj(128x128) -> global ----
    {
        float4 acc[2][2];
        #pragma unroll
        for (int n = 0; n < 2; n++) {
            float b0 = projb[n0 + n * 8 + 2 * tg];
            float b1 = projb[n0 + n * 8 + 2 * tg + 1];
            acc[0][n] = make_float4(b0, b1, b0, b1);
            acc[1][n] = acc[0][n];
        }
        #pragma unroll 4
        for (int kt = 0; kt < 8; kt++) {
            int kb = kt * 16;
            uint2 A[2][2];
            #pragma unroll
            for (int m = 0; m < 2; m++) {
                int r = (mb + m) * 16 + g;
                A[m][0] = *(const uint2*)&smh[OFF_X + r * SH + kb + 4 * tg];
                A[m][1] = *(const uint2*)&smh[OFF_X + (r + 8) * SH + kb + 4 * tg];
            }
            uint2 B[2];
            #pragma unroll
            for (int n = 0; n < 2; n++) {
                int nn = n0 + n * 8 + g;
                B[n] = *(const uint2*)&smh[OFF_W + nn * WSH + kb + 4 * tg];
            }
            #pragma unroll
            for (int m = 0; m < 2; m++)
                #pragma unroll
                for (int n = 0; n < 2; n++)
                    mma16(acc[m][n], A[m][0].x, A[m][1].x, A[m][0].y, A[m][1].y,
                          B[n].x, B[n].y);
        }

        #pragma unroll
        for (int m = 0; m < 2; m++) {
            #pragma unroll
            for (int rr = 0; rr < 2; rr++) {
                int r = (mb + m) * 16 + g + rr * 8;
                if (r < NTOK) {
                    #pragma unroll
                    for (int n = 0; n < 2; n++) {
                        float2 val = rr ? make_float2(acc[m][n].z, acc[m][n].w)
                                        : make_float2(acc[m][n].x, acc[m][n].y);
                        size_t o = (size_t)tokidx[r] * 128 + n0 + n * 8 + 2 * tg;
                        if (BRANCH != 0) {
                            float2 cur = *(const float2*)&out[o];
                            val.x += cur.x; val.y += cur.y;
                        }
                        *(float2*)&out[o] = val;
                    }
                }
            }
        }
    }
}

extern "C" void kernel_launch(void* const* d_in, const int* in_sizes, int n_in,
                              void* d_out, int out_size)
{
    const float* x         = (const float*)d_in[0];
    const float* qkv_w     = (const float*)d_in[1];
    const float* qkv_b     = (const float*)d_in[2];
    const float* qkv_th_w  = (const float*)d_in[3];
    const float* qkv_th_b  = (const float*)d_in[4];
    const float* qkv_tw_w  = (const float*)d_in[5];
    const float* qkv_tw_b  = (const float*)d_in[6];
    const float* proj_w    = (const float*)d_in[7];
    const float* proj_b    = (const float*)d_in[8];
    const float* proj_th_w = (const float*)d_in[9];
    const float* proj_th_b = (const float*)d_in[10];
    const float* proj_tw_w = (const float*)d_in[11];
    const float* proj_tw_b = (const float*)d_in[12];
    float* out = (float*)d_out;

    conv_weights<<<768, 256>>>(qkv_w, qkv_th_w, qkv_tw_w,
                               proj_w, proj_th_w, proj_tw_w);

    cudaFuncSetAttribute(win_attn_h<0, 49>,
                         cudaFuncAttributeMaxDynamicSharedMemorySize, SMEM_BYTES);
    cudaFuncSetAttribute(win_attn_h<1, 56>,
                         cudaFuncAttributeMaxDynamicSharedMemorySize, SMEM_BYTES);
    cudaFuncSetAttribute(win_attn_h<2, 56>,
                         cudaFuncAttributeMaxDynamicSharedMemorySize, SMEM_BYTES);

    // xy writes every output exactly once; th / tw accumulate (same stream).
    win_attn_h<0, 49><<<4096, 512, SMEM_BYTES>>>(x, qkv_b, proj_b, out);
    win_attn_h<1, 56><<<3584, 512, SMEM_BYTES>>>(x, qkv_th_b, proj_th_b, out);
    win_attn_h<2, 56><<<3584, 512, SMEM_BYTES>>>(x, qkv_tw_b, proj_tw_b, out);
}